// round 15
// baseline (speedup 1.0000x reference)
#include <cuda_runtime.h>
#include <cuda_fp16.h>
#include <mma.h>
#include <cstdint>

using namespace nvcuda;
typedef __half h16;

#define BB   128
#define NN   36
#define FEATD 2048
#define MIDD 517
#define HIDD 128
#define OUTD 1024
#define G4   4096
#define KP2  576
#define TSTEPS 36

#define C_LD   72                        // smem row stride in h16 (144B)

// ---- conv core: 128x64 tile, 8 warps, k-chunk 64, 2-stage, NT2 ----
#define C_OA   0
#define C_OBH  18432
#define C_OBL  27648
#define STGC   36864
#define DYN_CONV (2 * STGC)              // 73728

// ---- gin core: 128x256 tile, 16 warps (4x4), k-chunk 64, 2-stage ----
#define G_OA   0                         // A: 128*144 = 18432
#define G_OBH  18432                     // Bh: 256*144 = 36864
#define G_OBL  55296                     // Bl: 36864
#define G_STG  92160
#define DYN_GIN (2 * G_STG)              // 184320

// ---- step core: 128x32 tile, 8 warps, k-chunk 128, 2-stage, full-K ----
#define E_LD   136                       // row stride in h16 (272B)
#define E_OA   0                         // A: 128*272 = 34816
#define E_OB   34816                     // B: 32*272 = 8704
#define STG_E  43520
#define GIN_OFF (2 * STG_E)              // gates_in tile: 128*32*4 = 16384
#define DYN_STEP (2 * STG_E + 16384)     // 103424

// ---- fused skew+assign smem layout (floats) ----
#define SA_SF   0
#define SA_SWX  1152
#define SA_SWY  5376
#define SA_HX   9600
#define SA_HY   14208
#define SA_OUT  18816
#define SA_CS   20112
#define SA_LG   21408
#define SA_PS   22704
#define SA_DS   24000
#define SA_SA   25296
#define SA_W2   25332
#define SA_B1   25460
#define SA_TOT  25588
#define SA_DYN  (SA_TOT * 4)

// ------------------------- scratch -------------------------
__device__ float g_scale[BB];
__device__ float g_sigatt[BB * NN];
__device__ float g_feats[BB * MIDD * NN];                 // [b][m][n] fp32

__device__ __align__(16) h16 g_feat_hi[(size_t)BB * NN * FEATD];
__device__ __align__(16) h16 g_feat_lo[(size_t)BB * NN * FEATD];
__device__ __align__(16) h16 g_convw_h[512 * FEATD];
__device__ __align__(16) h16 g_wih_hi[(size_t)G4 * KP2];    // col = u*4+g
__device__ __align__(16) h16 g_wih_lo[(size_t)G4 * KP2];
__device__ __align__(16) h16 g_whh_h[(size_t)G4 * OUTD];    // reordered
__device__ __align__(16) h16 g_xh[(size_t)TSTEPS * BB * KP2];
__device__ float g_gates_in[(size_t)TSTEPS * BB * G4];      // reordered cols
__device__ __align__(16) h16 g_h0[BB * OUTD];
__device__ __align__(16) h16 g_h1[BB * OUTD];
__device__ float g_c[BB * OUTD];

// ------------------------- helpers -------------------------
__device__ __forceinline__ void split_write(float v, h16* hi, h16* lo) {
    h16 h = __float2half(v);
    *hi = h;
    *lo = __float2half(v - __half2float(h));
}

__device__ __forceinline__ void cp16(void* dst, const void* src) {
    unsigned d = (unsigned)__cvta_generic_to_shared(dst);
    asm volatile("cp.async.ca.shared.global [%0], [%1], 16;\n" ::"r"(d), "l"(src));
}

// ------------------------- init (scale + state) -------------------------
__global__ void k_init(const float* __restrict__ boxes) {
    int idx = blockIdx.x * blockDim.x + threadIdx.x;
    if (idx < BB) {
        const float* p = boxes + (size_t)idx * 4 * NN;
        float m = -1e30f;
        for (int i = 0; i < 4 * NN; i++) m = fmaxf(m, p[i]);
        g_scale[idx] = m;
    }
    if (idx < BB * OUTD) {
        g_h0[idx] = __float2half(0.f);
        g_c[idx] = 0.f;
    }
}

// ------------------------- fused prep (weights + features + head) -----------
#define PN1 ((size_t)512 * FEATD)
#define PN2 ((size_t)G4 * KP2)
#define PN3 ((size_t)G4 * OUTD)
#define PN4 ((size_t)BB * NN * FEATD)
#define PN5 ((size_t)BB * NN)
__global__ void k_prep(const float* __restrict__ cw, const float* __restrict__ wih,
                       const float* __restrict__ whh, const float* __restrict__ feat,
                       const float* __restrict__ boxes, const float* __restrict__ att) {
    size_t idx = (size_t)blockIdx.x * blockDim.x + threadIdx.x;
    if (idx < PN1) {
        g_convw_h[idx] = __float2half(cw[idx]);
    } else if (idx < PN1 + PN2) {
        size_t i = idx - PN1;
        int cr = (int)(i / KP2), k = (int)(i - (size_t)cr * KP2);
        int u = cr >> 2, g = cr & 3;
        float v = (k < MIDD) ? wih[(size_t)(g * OUTD + u) * MIDD + k] : 0.f;
        split_write(v, &g_wih_hi[i], &g_wih_lo[i]);
    } else if (idx < PN1 + PN2 + PN3) {
        size_t i = idx - PN1 - PN2;
        int cr = (int)(i / OUTD), k = (int)(i - (size_t)cr * OUTD);
        int u = cr >> 2, g = cr & 3;
        g_whh_h[i] = __float2half(whh[(size_t)(g * OUTD + u) * OUTD + k]);
    } else if (idx < PN1 + PN2 + PN3 + PN4) {
        size_t i = idx - PN1 - PN2 - PN3;
        split_write(feat[i], &g_feat_hi[i], &g_feat_lo[i]);
    } else if (idx < PN1 + PN2 + PN3 + PN4 + PN5) {
        int i = (int)(idx - PN1 - PN2 - PN3 - PN4);
        int b = i / NN, n = i - b * NN;
        float inv = 1.f / g_scale[b];
        for (int r = 0; r < 4; r++)
            g_feats[(size_t)b * MIDD * NN + r * NN + n] =
                boxes[(size_t)b * 4 * NN + r * NN + n] * inv;
        float a = att[i];
        g_feats[(size_t)b * MIDD * NN + 4 * NN + n] = a;
        g_sigatt[i] = 1.f / (1.f + expf(-a));
    }
}

// -------------- conv core: 128x64, 8 warps, k-chunk 64, 2-stage, NT2 --------
__device__ __forceinline__ float* gemm_conv(
    const h16* __restrict__ Ah,
    const h16* __restrict__ Bh, const h16* __restrict__ Bl,
    int lda, int ldb, int nch, int m0, int n0, char* sm)
{
    const int t = threadIdx.x, w = t >> 5;
    const int wm = w >> 1, wn = w & 1;

    wmma::fragment<wmma::accumulator, 16, 16, 16, float> acc[2][2];
#pragma unroll
    for (int i = 0; i < 2; i++)
#pragma unroll
        for (int j = 0; j < 2; j++) wmma::fill_fragment(acc[i][j], 0.f);

    auto issue = [&](int jc) {
        char* st = sm + (jc & 1) * STGC;
        int k0 = jc * 64;
#pragma unroll
        for (int u = 0; u < 8; u++) {
            int seg = t + u * 256;
            if (seg < 1024) {
                int row = seg >> 3, s = seg & 7;
                cp16(st + C_OA + row * 144 + s * 16,
                     Ah + (size_t)(m0 + row) * lda + k0 + s * 8);
            } else if (seg < 1536) {
                int x = seg - 1024;
                int row = x >> 3, s = x & 7;
                cp16(st + C_OBH + row * 144 + s * 16,
                     Bh + (size_t)(n0 + row) * ldb + k0 + s * 8);
            } else {
                int x = seg - 1536;
                int row = x >> 3, s = x & 7;
                cp16(st + C_OBL + row * 144 + s * 16,
                     Bl + (size_t)(n0 + row) * ldb + k0 + s * 8);
            }
        }
        asm volatile("cp.async.commit_group;\n" ::: "memory");
    };

    issue(0);
    for (int i = 0; i < nch; i++) {
        asm volatile("cp.async.wait_group 0;\n" ::: "memory");
        __syncthreads();
        if (i + 1 < nch) issue(i + 1);

        char* st = sm + (i & 1) * STGC;
        h16* sA = (h16*)(st + C_OA);
        h16* sBh = (h16*)(st + C_OBH);
        h16* sBl = (h16*)(st + C_OBL);
#pragma unroll
        for (int ks = 0; ks < 4; ks++) {
            const int kk = ks * 16;
            wmma::fragment<wmma::matrix_a, 16, 16, 16, h16, wmma::row_major> a[2];
            wmma::fragment<wmma::matrix_b, 16, 16, 16, h16, wmma::col_major> bh[2];
#pragma unroll
            for (int i2 = 0; i2 < 2; i2++) {
                wmma::load_matrix_sync(a[i2], &sA[(wm * 32 + i2 * 16) * C_LD + kk], C_LD);
                wmma::load_matrix_sync(bh[i2], &sBh[(wn * 32 + i2 * 16) * C_LD + kk], C_LD);
            }
#pragma unroll
            for (int i2 = 0; i2 < 2; i2++)
#pragma unroll
                for (int j2 = 0; j2 < 2; j2++)
                    wmma::mma_sync(acc[i2][j2], a[i2], bh[j2], acc[i2][j2]);
            wmma::fragment<wmma::matrix_b, 16, 16, 16, h16, wmma::col_major> bl[2];
#pragma unroll
            for (int i2 = 0; i2 < 2; i2++)
                wmma::load_matrix_sync(bl[i2], &sBl[(wn * 32 + i2 * 16) * C_LD + kk], C_LD);
#pragma unroll
            for (int i2 = 0; i2 < 2; i2++)
#pragma unroll
                for (int j2 = 0; j2 < 2; j2++)
                    wmma::mma_sync(acc[i2][j2], a[i2], bl[j2], acc[i2][j2]);
        }
    }
    __syncthreads();
    float* Cs = (float*)sm;
#pragma unroll
    for (int i2 = 0; i2 < 2; i2++)
#pragma unroll
        for (int j2 = 0; j2 < 2; j2++)
            wmma::store_matrix_sync(&Cs[(wm * 32 + i2 * 16) * 64 + wn * 32 + j2 * 16],
                                    acc[i2][j2], 64, wmma::mem_row_major);
    __syncthreads();
    return Cs;
}

// ------- gin core: 128x256, 16 warps (4x4), k-chunk 64, 2-stage, NT2 --------
__device__ __forceinline__ float* gemm_gin(
    const h16* __restrict__ Ah,
    const h16* __restrict__ Bh, const h16* __restrict__ Bl,
    int lda, int ldb, int nch, int m0, int n0, char* sm)
{
    const int t = threadIdx.x, w = t >> 5;
    const int wm = w >> 2, wn = w & 3;      // 4x4; warp tile 32x64

    wmma::fragment<wmma::accumulator, 16, 16, 16, float> acc[2][4];
#pragma unroll
    for (int i = 0; i < 2; i++)
#pragma unroll
        for (int j = 0; j < 4; j++) wmma::fill_fragment(acc[i][j], 0.f);

    auto issue = [&](int jc) {
        char* st = sm + (jc & 1) * G_STG;
        int k0 = jc * 64;
        // 5760 16B-segments total: A 1152 | Bh 2304 | Bl 2304
#pragma unroll
        for (int u = 0; u < 12; u++) {
            int seg = t + u * 512;
            if (seg >= 5760) break;
            if (seg < 1152) {
                int row = seg / 9, s = seg - (seg / 9) * 9;   // 9 segs per 144B row
                cp16(st + G_OA + row * 144 + s * 16,
                     Ah + (size_t)(m0 + row) * lda + k0 + s * 8);
            } else if (seg < 3456) {
                int x = seg - 1152;
                int row = x / 9, s = x - (x / 9) * 9;
                cp16(st + G_OBH + row * 144 + s * 16,
                     Bh + (size_t)(n0 + row) * ldb + k0 + s * 8);
            } else {
                int x = seg - 3456;
                int row = x / 9, s = x - (x / 9) * 9;
                cp16(st + G_OBL + row * 144 + s * 16,
                     Bl + (size_t)(n0 + row) * ldb + k0 + s * 8);
            }
        }
        asm volatile("cp.async.commit_group;\n" ::: "memory");
    };

    issue(0);
    for (int i = 0; i < nch; i++) {
        asm volatile("cp.async.wait_group 0;\n" ::: "memory");
        __syncthreads();
        if (i + 1 < nch) issue(i + 1);

        char* st = sm + (i & 1) * G_STG;
        h16* sA = (h16*)(st + G_OA);
        h16* sBh = (h16*)(st + G_OBH);
        h16* sBl = (h16*)(st + G_OBL);
#pragma unroll
        for (int ks = 0; ks < 4; ks++) {
            const int kk = ks * 16;
            wmma::fragment<wmma::matrix_a, 16, 16, 16, h16, wmma::row_major> a[2];
#pragma unroll
            for (int i2 = 0; i2 < 2; i2++)
                wmma::load_matrix_sync(a[i2], &sA[(wm * 32 + i2 * 16) * C_LD + kk], C_LD);
#pragma unroll
            for (int j2 = 0; j2 < 4; j2++) {
                wmma::fragment<wmma::matrix_b, 16, 16, 16, h16, wmma::col_major> b;
                wmma::load_matrix_sync(b, &sBh[(wn * 64 + j2 * 16) * C_LD + kk], C_LD);
#pragma unroll
                for (int i2 = 0; i2 < 2; i2++)
                    wmma::mma_sync(acc[i2][j2], a[i2], b, acc[i2][j2]);
            }
#pragma unroll
            for (int j2 = 0; j2 < 4; j2++) {
                wmma::fragment<wmma::matrix_b, 16, 16, 16, h16, wmma::col_major> b;
                wmma::load_matrix_sync(b, &sBl[(wn * 64 + j2 * 16) * C_LD + kk], C_LD);
#pragma unroll
                for (int i2 = 0; i2 < 2; i2++)
                    wmma::mma_sync(acc[i2][j2], a[i2], b, acc[i2][j2]);
            }
        }
    }
    __syncthreads();
    float* Cs = (float*)sm;   // 128*256*4 = 128KB, aliases consumed stages
#pragma unroll
    for (int i2 = 0; i2 < 2; i2++)
#pragma unroll
        for (int j2 = 0; j2 < 4; j2++)
            wmma::store_matrix_sync(&Cs[(wm * 32 + i2 * 16) * 256 + wn * 64 + j2 * 16],
                                    acc[i2][j2], 256, wmma::mem_row_major);
    __syncthreads();
    return Cs;
}

// ------- step core: 128x32 tile, 8 warps (4x2), k-chunk 128, 2-stage --------
__device__ __forceinline__ float* gemm_stepN32(
    const h16* __restrict__ Ah, const h16* __restrict__ Bh,
    int lda, int ldb, int nch, int n0, char* sm)
{
    const int t = threadIdx.x, w = t >> 5;
    const int wm = w >> 1, wn = w & 1;    // warp tile 32x16

    wmma::fragment<wmma::accumulator, 16, 16, 16, float> acc[2];
    wmma::fill_fragment(acc[0], 0.f);
    wmma::fill_fragment(acc[1], 0.f);

    auto issue = [&](int jc) {
        char* st = sm + (jc & 1) * STG_E;
        int k0 = jc * 128;
#pragma unroll
        for (int u = 0; u < 10; u++) {
            int seg = t + u * 256;
            if (seg < 2048) {
                int row = seg >> 4, s = seg & 15;
                cp16(st + E_OA + row * 272 + s * 16,
                     Ah + (size_t)row * lda + k0 + s * 8);
            } else {
                int x = seg - 2048;
                int row = x >> 4, s = x & 15;
                cp16(st + E_OB + row * 272 + s * 16,
                     Bh + (size_t)(n0 + row) * ldb + k0 + s * 8);
            }
        }
        asm volatile("cp.async.commit_group;\n" ::: "memory");
    };

    issue(0);
    for (int i = 0; i < nch; i++) {
        asm volatile("cp.async.wait_group 0;\n" ::: "memory");
        __syncthreads();
        if (i + 1 < nch) issue(i + 1);

        char* st = sm + (i & 1) * STG_E;
        h16* sA = (h16*)(st + E_OA);
        h16* sB = (h16*)(st + E_OB);
#pragma unroll
        for (int ks = 0; ks < 8; ks++) {
            const int kk = ks * 16;
            wmma::fragment<wmma::matrix_a, 16, 16, 16, h16, wmma::row_major> a[2];
            wmma::fragment<wmma::matrix_b, 16, 16, 16, h16, wmma::col_major> b;
            wmma::load_matrix_sync(a[0], &sA[(wm * 32) * E_LD + kk], E_LD);
            wmma::load_matrix_sync(a[1], &sA[(wm * 32 + 16) * E_LD + kk], E_LD);
            wmma::load_matrix_sync(b, &sB[(wn * 16) * E_LD + kk], E_LD);
            wmma::mma_sync(acc[0], a[0], b, acc[0]);
            wmma::mma_sync(acc[1], a[1], b, acc[1]);
        }
    }
    __syncthreads();
    float* Cs = (float*)sm;   // 16KB, aliases consumed stage
    wmma::store_matrix_sync(&Cs[(wm * 32) * 32 + wn * 16], acc[0], 32,
                            wmma::mem_row_major);
    wmma::store_matrix_sync(&Cs[(wm * 32 + 16) * 32 + wn * 16], acc[1], 32,
                            wmma::mem_row_major);
    __syncthreads();
    return Cs;
}

// ------------------------- conv GEMM -------------------------
__global__ __launch_bounds__(256) void k_conv(const float* __restrict__ convb) {
    extern __shared__ char sm[];
    int m0 = blockIdx.x * 128, n0 = blockIdx.y * 64;
    float* Cs = gemm_conv(g_convw_h, g_feat_hi, g_feat_lo,
                          FEATD, FEATD, FEATD / 64, m0, n0, sm);
    for (int idx = threadIdx.x; idx < 128 * 64; idx += 256) {
        int r = idx >> 6, cc = idx & 63;
        int m = m0 + r, col = n0 + cc;
        int b = col / NN, n = col - b * NN;
        g_feats[(size_t)b * MIDD * NN + (5 + m) * NN + n] = Cs[idx] + convb[m];
    }
}

// ------------------------- input-gate GEMM -------------------------
__global__ __launch_bounds__(512) void k_gin(const float* __restrict__ bih,
                                             const float* __restrict__ bhh) {
    extern __shared__ char sm[];
    int m0 = blockIdx.x * 128, n0 = blockIdx.y * 256;
    float* Cs = gemm_gin(g_xh, g_wih_hi, g_wih_lo,
                         KP2, KP2, KP2 / 64, m0, n0, sm);
    for (int idx = threadIdx.x; idx < 128 * 256; idx += 512) {
        int r = idx >> 8, cc = idx & 255;
        int row = m0 + r, col = n0 + cc;
        int orig = (col & 3) * OUTD + (col >> 2);
        g_gates_in[(size_t)row * G4 + col] = Cs[idx] + bih[orig] + bhh[orig];
    }
}

// ------------------------- recurrent step: full-K N32 + fused update --------
__global__ __launch_bounds__(256) void k_step(int s, float* __restrict__ outc) {
    extern __shared__ char sm[];
    const int n0 = blockIdx.x * 32;     // 128 tiles of N=32
    const int t = threadIdx.x;

    const h16* hin = (s & 1) ? g_h1 : g_h0;
    h16* hout = (s & 1) ? g_h0 : g_h1;

    // prefetch this block's gates_in tile [128 x 32] fp32 (overlaps GEMM)
    {
        const float* gin = g_gates_in + (size_t)s * BB * G4;
        char* sg = sm + GIN_OFF;
#pragma unroll
        for (int u = 0; u < 4; u++) {
            int seg = t + u * 256;
            int row = seg >> 3, ss = seg & 7;
            cp16(sg + row * 128 + ss * 16,
                 gin + (size_t)row * G4 + n0 + ss * 4);
        }
        asm volatile("cp.async.commit_group;\n" ::: "memory");
    }

    float* Cs = gemm_stepN32(hin, g_whh_h, OUTD, OUTD, OUTD / 128, n0, sm);

    const float* sg = (const float*)(sm + GIN_OFF);
    for (int p = t; p < 1024; p += 256) {
        int b = p >> 3, lu = p & 7;
        const float* cr = &Cs[b * 32 + lu * 4];
        float4 gv = *(const float4*)(sg + b * 32 + lu * 4);
        float ig = cr[0] + gv.x;
        float fg = cr[1] + gv.y;
        float gg = cr[2] + gv.z;
        float og = cr[3] + gv.w;
        float si = 1.f / (1.f + expf(-ig));
        float sf = 1.f / (1.f + expf(-fg));
        float so = 1.f / (1.f + expf(-og));
        int u = (n0 >> 2) + lu;
        int ci = b * OUTD + u;
        float c = sf * g_c[ci] + si * tanhf(gg);
        g_c[ci] = c;
        hout[ci] = __float2half(so * tanhf(c));
        if (outc) outc[ci] = c;
    }
}

// ------------------------- fused skew + assignment + mix --------------------
__global__ __launch_bounds__(512) void k_sa(const float* __restrict__ wx,
                                            const float* __restrict__ wy,
                                            const float* __restrict__ b1,
                                            const float* __restrict__ w2,
                                            const float* __restrict__ b2p,
                                            const float* __restrict__ lrp) {
    extern __shared__ float S[];
    int b = blockIdx.x, t = threadIdx.x;
    const float* fb = g_feats + (size_t)b * MIDD * NN;

    {
        int h = t & 127, g = t >> 7;
        float ax[9], ay[9];
#pragma unroll
        for (int n = 0; n < 9; n++) { ax[n] = 0.f; ay[n] = 0.f; }
        for (int mc = 0; mc < MIDD; mc += 32) {
            int mlen = min(32, MIDD - mc);
            for (int i = t; i < mlen * NN; i += 512) S[SA_SF + i] = fb[mc * NN + i];
            if (g == 0) {
                for (int j = 0; j < mlen; j++)
                    S[SA_SWX + h * 33 + j] = wx[(size_t)h * MIDD + mc + j];
            } else if (g == 1) {
                for (int j = 0; j < mlen; j++)
                    S[SA_SWY + h * 33 + j] = wy[(size_t)h * MIDD + mc + j];
            }
            __syncthreads();
            for (int j = 0; j < mlen; j++) {
                float wxv = S[SA_SWX + h * 33 + j];
                float wyv = S[SA_SWY + h * 33 + j];
                const float* sr = &S[SA_SF + j * NN + g * 9];
#pragma unroll
                for (int n = 0; n < 9; n++) {
                    float fv = sr[n];
                    ax[n] += wxv * fv;
                    ay[n] += wyv * fv;
                }
            }
            __syncthreads();
        }
#pragma unroll
        for (int n = 0; n < 9; n++) {
            S[SA_HX + h * NN + g * 9 + n] = ax[n];
            S[SA_HY + h * NN + g * 9 + n] = ay[n];
        }
    }
    if (t < 128) { S[SA_W2 + t] = w2[t]; S[SA_B1 + t] = b1[t]; }
    if (t < 36) S[SA_SA + t] = g_sigatt[b * NN + t];
    __syncthreads();

    float b2v = b2p[0];
    for (int p = t; p < 1296; p += 512) {
        int i = p / 36, j = p - i * 36;
        float s = 0.f;
#pragma unroll 8
        for (int h = 0; h < HIDD; h++) {
            float v = S[SA_HX + h * NN + i] + S[SA_HY + h * NN + j] + S[SA_B1 + h];
            s += S[SA_W2 + h] * fmaxf(v, 0.f);
        }
        S[SA_OUT + p] = s + b2v;
    }
    __syncthreads();
    for (int p = t; p < 1296; p += 512) {
        int i = p / 36, j = p - i * 36;
        S[SA_CS + p] = S[SA_OUT + p] - S[SA_OUT + j * 36 + i];
        S[SA_LG + p] = 0.f;
    }
    __syncthreads();

    float lrabs = fabsf(lrp[0]);
    for (int it = 0; it < 3; it++) {
        if (t < 36) {
            float mx = -1e30f;
            for (int j = 0; j < 36; j++) mx = fmaxf(mx, S[SA_LG + t * 36 + j]);
            float sum = 0.f;
            for (int j = 0; j < 36; j++) {
                float e = expf(S[SA_LG + t * 36 + j] - mx);
                S[SA_PS + t * 36 + j] = e;
                sum += e;
            }
            float inv = 1.f / sum;
            for (int j = 0; j < 36; j++) S[SA_PS + t * 36 + j] *= inv;
        }
        __syncthreads();
        if (t < 36) {
            int l = t;
            float tot = 0.f;
            for (int i = 0; i < 36; i++) tot += S[SA_PS + i * 36 + l];
            float run = 0.f;
            for (int i = 0; i < 36; i++) {
                float p = S[SA_PS + i * 36 + l];
                run += p;
                S[SA_DS + i * 36 + l] = tot - 2.f * run + p;
            }
        }
        __syncthreads();
        for (int p = t; p < 1296; p += 512) {
            int i = p / 36, j = p - i * 36;
            float gsum = 0.f;
#pragma unroll
            for (int l = 0; l < 36; l++)
                gsum += S[SA_DS + i * 36 + l] * S[SA_CS + j * 36 + l];
            S[SA_LG + p] -= lrabs * gsum;
        }
        __syncthreads();
    }
    if (t < 36) {
        float mx = -1e30f;
        for (int j = 0; j < 36; j++) mx = fmaxf(mx, S[SA_LG + t * 36 + j]);
        float sum = 0.f;
        for (int j = 0; j < 36; j++) {
            float e = expf(S[SA_LG + t * 36 + j] - mx);
            S[SA_PS + t * 36 + j] = e;
            sum += e;
        }
        float inv = 1.f / sum;
        for (int j = 0; j < 36; j++) S[SA_PS + t * 36 + j] *= inv;
    }
    __syncthreads();

    for (int p = t; p < MIDD * NN; p += 512) {
        int c = p / 36, i = p - c * 36;
        float s = 0.f;
#pragma unroll
        for (int l = 0; l < 36; l++)
            s += fb[c * 36 + l] * S[SA_SA + l] * S[SA_PS + i * 36 + l];
        g_xh[((size_t)i * BB + b) * KP2 + c] = __float2half(s);
    }
    for (int p = t; p < (KP2 - MIDD) * NN; p += 512) {
        int c = MIDD + p / 36, i = p % 36;
        g_xh[((size_t)i * BB + b) * KP2 + c] = __float2half(0.f);
    }
}

// ------------------------- launch -------------------------
extern "C" void kernel_launch(void* const* d_in, const int* in_sizes, int n_in,
                              void* d_out, int out_size) {
    const float* boxes     = (const float*)d_in[0];
    const float* attention = (const float*)d_in[1];
    const float* features  = (const float*)d_in[2];
    const float* conv_w    = (const float*)d_in[3];
    const float* conv_b    = (const float*)d_in[4];
    const float* skew_wx   = (const float*)d_in[5];
    const float* skew_wy   = (const float*)d_in[6];
    const float* skew_b1   = (const float*)d_in[7];
    const float* skew_w2   = (const float*)d_in[8];
    const float* skew_b2   = (const float*)d_in[9];
    const float* w_ih      = (const float*)d_in[10];
    const float* w_hh      = (const float*)d_in[11];
    const float* b_ih      = (const float*)d_in[12];
    const float* b_hh      = (const float*)d_in[13];
    const float* lr        = (const float*)d_in[14];

    static int attr_done = 0;
    if (!attr_done) {
        cudaFuncSetAttribute(k_conv, cudaFuncAttributeMaxDynamicSharedMemorySize, DYN_CONV);
        cudaFuncSetAttribute(k_gin,  cudaFuncAttributeMaxDynamicSharedMemorySize, DYN_GIN);
        cudaFuncSetAttribute(k_step, cudaFuncAttributeMaxDynamicSharedMemorySize, DYN_STEP);
        cudaFuncSetAttribute(k_sa,   cudaFuncAttributeMaxDynamicSharedMemorySize, SA_DYN);
        attr_done = 1;
    }

    k_init<<<(BB * OUTD + 255) / 256, 256>>>(boxes);
    {
        size_t total = PN1 + PN2 + PN3 + PN4 + PN5;
        k_prep<<<(unsigned)((total + 511) / 512), 512>>>(
            conv_w, w_ih, w_hh, features, boxes, attention);
    }
    k_conv<<<dim3(4, 72), 256, DYN_CONV>>>(conv_b);
    k_sa<<<BB, 512, SA_DYN>>>(skew_wx, skew_wy, skew_b1, skew_w2, skew_b2, lr);
    k_gin<<<dim3(36, 16), 512, DYN_GIN>>>(b_ih, b_hh);

    for (int s = 0; s < TSTEPS; s++) {
        k_step<<<128, 256, DYN_STEP>>>(s, s == TSTEPS - 1 ? (float*)d_out : nullptr);
    }
}

// round 16
// speedup vs baseline: 1.1247x; 1.1247x over previous
#include <cuda_runtime.h>
#include <cuda_fp16.h>
#include <mma.h>
#include <cstdint>

using namespace nvcuda;
typedef __half h16;

#define BB   128
#define NN   36
#define FEATD 2048
#define MIDD 517
#define HIDD 128
#define OUTD 1024
#define G4   4096
#define KP2  576
#define COLS 4608          // BB*NN
#define TSTEPS 36

#define C_LD   72                        // smem row stride in h16 (144B)

// ---- conv core: 128x64 tile, 8 warps, k-chunk 64, 2-stage, NT2 ----
#define C_OA   0
#define C_OBH  18432
#define C_OBL  27648
#define STGC   36864
#define DYN_CONV (2 * STGC)              // 73728

// ---- gin core: 128x128 tile, 16 warps, k-chunk 64, 2-stage ----
#define D_OA   0
#define D_OBH  18432
#define D_OBL  36864
#define D_STG  55296
#define DYN_GIN (2 * D_STG)              // 110592

// ---- skew core: 128x64 tile, 8 warps, k-chunk 64, 2-stage, 3-term ----
#define SK_OAH 0                         // Ah: 128*144 = 18432
#define SK_OAL 18432                     // Al: 18432
#define SK_OBH 36864                     // Bh: 64*144 = 9216
#define SK_OBL 46080                     // Bl: 9216
#define SK_STG 55296
#define DYN_SKEW (2 * SK_STG)            // 110592

// ---- step core: 128x32 tile, 8 warps, k-chunk 128, 2-stage, full-K ----
#define E_LD   136                       // row stride in h16 (272B)
#define E_OA   0                         // A: 128*272 = 34816
#define E_OB   34816                     // B: 32*272 = 8704
#define STG_E  43520
#define GIN_OFF (2 * STG_E)              // gates_in tile: 128*32*4 = 16384
#define DYN_STEP (2 * STG_E + 16384)     // 103424

// ---- k_sa smem layout (floats) — phase 1 removed ----
#define SA_HX   0                        // 4608
#define SA_HY   4608
#define SA_OUT  9216
#define SA_CS   10512
#define SA_LG   11808
#define SA_PS   13104
#define SA_DS   14400
#define SA_SA   15696
#define SA_W2   15732
#define SA_B1   15860
#define SA_TOT  15988
#define SA_DYN  (SA_TOT * 4)             // 63952

// ------------------------- scratch -------------------------
__device__ float g_scale[BB];
__device__ float g_sigatt[BB * NN];
__device__ float g_feats[BB * MIDD * NN];                 // [b][m][n] fp32 (mix)

__device__ __align__(16) h16 g_feat_hi[(size_t)BB * NN * FEATD];
__device__ __align__(16) h16 g_feat_lo[(size_t)BB * NN * FEATD];
__device__ __align__(16) h16 g_convw_h[512 * FEATD];
__device__ __align__(16) h16 g_ft_hi[(size_t)COLS * KP2];   // feats^T [col][m]
__device__ __align__(16) h16 g_ft_lo[(size_t)COLS * KP2];
__device__ __align__(16) h16 g_wx_hi[HIDD * KP2];
__device__ __align__(16) h16 g_wx_lo[HIDD * KP2];
__device__ __align__(16) h16 g_wy_hi[HIDD * KP2];
__device__ __align__(16) h16 g_wy_lo[HIDD * KP2];
__device__ float g_hx_all[(size_t)HIDD * COLS];             // [h][col]
__device__ float g_hy_all[(size_t)HIDD * COLS];
__device__ __align__(16) h16 g_wih_hi[(size_t)G4 * KP2];    // col = u*4+g
__device__ __align__(16) h16 g_wih_lo[(size_t)G4 * KP2];
__device__ __align__(16) h16 g_whh_h[(size_t)G4 * OUTD];    // reordered
__device__ __align__(16) h16 g_xh[(size_t)TSTEPS * BB * KP2];
__device__ float g_gates_in[(size_t)TSTEPS * BB * G4];      // reordered cols
__device__ __align__(16) h16 g_h0[BB * OUTD];
__device__ __align__(16) h16 g_h1[BB * OUTD];
__device__ float g_c[BB * OUTD];

// ------------------------- helpers -------------------------
__device__ __forceinline__ void split_write(float v, h16* hi, h16* lo) {
    h16 h = __float2half(v);
    *hi = h;
    *lo = __float2half(v - __half2float(h));
}

__device__ __forceinline__ void cp16(void* dst, const void* src) {
    unsigned d = (unsigned)__cvta_generic_to_shared(dst);
    asm volatile("cp.async.ca.shared.global [%0], [%1], 16;\n" ::"r"(d), "l"(src));
}

// ------------------------- init (scale + state) -------------------------
__global__ void k_init(const float* __restrict__ boxes) {
    int idx = blockIdx.x * blockDim.x + threadIdx.x;
    if (idx < BB) {
        const float* p = boxes + (size_t)idx * 4 * NN;
        float m = -1e30f;
        for (int i = 0; i < 4 * NN; i++) m = fmaxf(m, p[i]);
        g_scale[idx] = m;
    }
    if (idx < BB * OUTD) {
        g_h0[idx] = __float2half(0.f);
        g_c[idx] = 0.f;
    }
}

// ---------------- fused prep (weights + features + head + pads) -------------
#define PN1 ((size_t)512 * FEATD)
#define PN2 ((size_t)G4 * KP2)
#define PN3 ((size_t)G4 * OUTD)
#define PN4 ((size_t)BB * NN * FEATD)
#define PN5 ((size_t)BB * NN)
#define PN6 ((size_t)2 * HIDD * KP2)
#define PN7 ((size_t)COLS * (KP2 - MIDD))
__global__ void k_prep(const float* __restrict__ cw, const float* __restrict__ wih,
                       const float* __restrict__ whh, const float* __restrict__ feat,
                       const float* __restrict__ boxes, const float* __restrict__ att,
                       const float* __restrict__ wx, const float* __restrict__ wy) {
    size_t idx = (size_t)blockIdx.x * blockDim.x + threadIdx.x;
    if (idx < PN1) {
        g_convw_h[idx] = __float2half(cw[idx]);
    } else if (idx < PN1 + PN2) {
        size_t i = idx - PN1;
        int cr = (int)(i / KP2), k = (int)(i - (size_t)cr * KP2);
        int u = cr >> 2, g = cr & 3;
        float v = (k < MIDD) ? wih[(size_t)(g * OUTD + u) * MIDD + k] : 0.f;
        split_write(v, &g_wih_hi[i], &g_wih_lo[i]);
    } else if (idx < PN1 + PN2 + PN3) {
        size_t i = idx - PN1 - PN2;
        int cr = (int)(i / OUTD), k = (int)(i - (size_t)cr * OUTD);
        int u = cr >> 2, g = cr & 3;
        g_whh_h[i] = __float2half(whh[(size_t)(g * OUTD + u) * OUTD + k]);
    } else if (idx < PN1 + PN2 + PN3 + PN4) {
        size_t i = idx - PN1 - PN2 - PN3;
        split_write(feat[i], &g_feat_hi[i], &g_feat_lo[i]);
    } else if (idx < PN1 + PN2 + PN3 + PN4 + PN5) {
        int i = (int)(idx - PN1 - PN2 - PN3 - PN4);   // i == col
        int b = i / NN, n = i - b * NN;
        float inv = 1.f / g_scale[b];
        for (int r = 0; r < 4; r++) {
            float v = boxes[(size_t)b * 4 * NN + r * NN + n] * inv;
            g_feats[(size_t)b * MIDD * NN + r * NN + n] = v;
            split_write(v, &g_ft_hi[(size_t)i * KP2 + r], &g_ft_lo[(size_t)i * KP2 + r]);
        }
        float a = att[i];
        g_feats[(size_t)b * MIDD * NN + 4 * NN + n] = a;
        split_write(a, &g_ft_hi[(size_t)i * KP2 + 4], &g_ft_lo[(size_t)i * KP2 + 4]);
        g_sigatt[i] = 1.f / (1.f + expf(-a));
    } else if (idx < PN1 + PN2 + PN3 + PN4 + PN5 + PN6) {
        size_t i = idx - PN1 - PN2 - PN3 - PN4 - PN5;
        int sel = (int)(i / (HIDD * KP2));
        int j = (int)(i - (size_t)sel * HIDD * KP2);
        int h = j / KP2, k = j - h * KP2;
        const float* src = sel ? wy : wx;
        float v = (k < MIDD) ? src[(size_t)h * MIDD + k] : 0.f;
        if (sel) split_write(v, &g_wy_hi[j], &g_wy_lo[j]);
        else     split_write(v, &g_wx_hi[j], &g_wx_lo[j]);
    } else if (idx < PN1 + PN2 + PN3 + PN4 + PN5 + PN6 + PN7) {
        size_t i = idx - PN1 - PN2 - PN3 - PN4 - PN5 - PN6;
        int col = (int)(i / (KP2 - MIDD));
        int m = MIDD + (int)(i - (size_t)col * (KP2 - MIDD));
        g_ft_hi[(size_t)col * KP2 + m] = __float2half(0.f);
        g_ft_lo[(size_t)col * KP2 + m] = __float2half(0.f);
    }
}

// -------------- conv core: 128x64, 8 warps, k-chunk 64, 2-stage, NT2 --------
__device__ __forceinline__ float* gemm_conv(
    const h16* __restrict__ Ah,
    const h16* __restrict__ Bh, const h16* __restrict__ Bl,
    int lda, int ldb, int nch, int m0, int n0, char* sm)
{
    const int t = threadIdx.x, w = t >> 5;
    const int wm = w >> 1, wn = w & 1;

    wmma::fragment<wmma::accumulator, 16, 16, 16, float> acc[2][2];
#pragma unroll
    for (int i = 0; i < 2; i++)
#pragma unroll
        for (int j = 0; j < 2; j++) wmma::fill_fragment(acc[i][j], 0.f);

    auto issue = [&](int jc) {
        char* st = sm + (jc & 1) * STGC;
        int k0 = jc * 64;
#pragma unroll
        for (int u = 0; u < 8; u++) {
            int seg = t + u * 256;
            if (seg < 1024) {
                int row = seg >> 3, s = seg & 7;
                cp16(st + C_OA + row * 144 + s * 16,
                     Ah + (size_t)(m0 + row) * lda + k0 + s * 8);
            } else if (seg < 1536) {
                int x = seg - 1024;
                int row = x >> 3, s = x & 7;
                cp16(st + C_OBH + row * 144 + s * 16,
                     Bh + (size_t)(n0 + row) * ldb + k0 + s * 8);
            } else {
                int x = seg - 1536;
                int row = x >> 3, s = x & 7;
                cp16(st + C_OBL + row * 144 + s * 16,
                     Bl + (size_t)(n0 + row) * ldb + k0 + s * 8);
            }
        }
        asm volatile("cp.async.commit_group;\n" ::: "memory");
    };

    issue(0);
    for (int i = 0; i < nch; i++) {
        asm volatile("cp.async.wait_group 0;\n" ::: "memory");
        __syncthreads();
        if (i + 1 < nch) issue(i + 1);

        char* st = sm + (i & 1) * STGC;
        h16* sA = (h16*)(st + C_OA);
        h16* sBh = (h16*)(st + C_OBH);
        h16* sBl = (h16*)(st + C_OBL);
#pragma unroll
        for (int ks = 0; ks < 4; ks++) {
            const int kk = ks * 16;
            wmma::fragment<wmma::matrix_a, 16, 16, 16, h16, wmma::row_major> a[2];
            wmma::fragment<wmma::matrix_b, 16, 16, 16, h16, wmma::col_major> bh[2];
#pragma unroll
            for (int i2 = 0; i2 < 2; i2++) {
                wmma::load_matrix_sync(a[i2], &sA[(wm * 32 + i2 * 16) * C_LD + kk], C_LD);
                wmma::load_matrix_sync(bh[i2], &sBh[(wn * 32 + i2 * 16) * C_LD + kk], C_LD);
            }
#pragma unroll
            for (int i2 = 0; i2 < 2; i2++)
#pragma unroll
                for (int j2 = 0; j2 < 2; j2++)
                    wmma::mma_sync(acc[i2][j2], a[i2], bh[j2], acc[i2][j2]);
            wmma::fragment<wmma::matrix_b, 16, 16, 16, h16, wmma::col_major> bl[2];
#pragma unroll
            for (int i2 = 0; i2 < 2; i2++)
                wmma::load_matrix_sync(bl[i2], &sBl[(wn * 32 + i2 * 16) * C_LD + kk], C_LD);
#pragma unroll
            for (int i2 = 0; i2 < 2; i2++)
#pragma unroll
                for (int j2 = 0; j2 < 2; j2++)
                    wmma::mma_sync(acc[i2][j2], a[i2], bl[j2], acc[i2][j2]);
        }
    }
    __syncthreads();
    float* Cs = (float*)sm;
#pragma unroll
    for (int i2 = 0; i2 < 2; i2++)
#pragma unroll
        for (int j2 = 0; j2 < 2; j2++)
            wmma::store_matrix_sync(&Cs[(wm * 32 + i2 * 16) * 64 + wn * 32 + j2 * 16],
                                    acc[i2][j2], 64, wmma::mem_row_major);
    __syncthreads();
    return Cs;
}

// -------------- gin core: 128x128, 16 warps, k-chunk 64, 2-stage ------------
__device__ __forceinline__ float* gemm_big(
    const h16* __restrict__ Ah,
    const h16* __restrict__ Bh, const h16* __restrict__ Bl,
    int lda, int ldb, int nch, int m0, int n0, char* sm)
{
    const int t = threadIdx.x, w = t >> 5;
    const int wm = w >> 2, wn = w & 3;

    wmma::fragment<wmma::accumulator, 16, 16, 16, float> acc[2][2];
#pragma unroll
    for (int i = 0; i < 2; i++)
#pragma unroll
        for (int j = 0; j < 2; j++) wmma::fill_fragment(acc[i][j], 0.f);

    auto issue = [&](int jc) {
        char* st = sm + (jc & 1) * D_STG;
        int k0 = jc * 64;
#pragma unroll
        for (int u = 0; u < 6; u++) {
            int seg = t + u * 512;
            if (seg < 1024) {
                int row = seg >> 3, s = seg & 7;
                cp16(st + D_OA + row * 144 + s * 16,
                     Ah + (size_t)(m0 + row) * lda + k0 + s * 8);
            } else if (seg < 2048) {
                int x = seg - 1024;
                int row = x >> 3, s = x & 7;
                cp16(st + D_OBH + row * 144 + s * 16,
                     Bh + (size_t)(n0 + row) * ldb + k0 + s * 8);
            } else {
                int x = seg - 2048;
                int row = x >> 3, s = x & 7;
                cp16(st + D_OBL + row * 144 + s * 16,
                     Bl + (size_t)(n0 + row) * ldb + k0 + s * 8);
            }
        }
        asm volatile("cp.async.commit_group;\n" ::: "memory");
    };

    issue(0);
    for (int i = 0; i < nch; i++) {
        asm volatile("cp.async.wait_group 0;\n" ::: "memory");
        __syncthreads();
        if (i + 1 < nch) issue(i + 1);

        char* st = sm + (i & 1) * D_STG;
        h16* sA = (h16*)(st + D_OA);
        h16* sBh = (h16*)(st + D_OBH);
        h16* sBl = (h16*)(st + D_OBL);
#pragma unroll
        for (int ks = 0; ks < 4; ks++) {
            const int kk = ks * 16;
            wmma::fragment<wmma::matrix_a, 16, 16, 16, h16, wmma::row_major> a[2];
            wmma::fragment<wmma::matrix_b, 16, 16, 16, h16, wmma::col_major> bh[2];
#pragma unroll
            for (int i2 = 0; i2 < 2; i2++) {
                wmma::load_matrix_sync(a[i2], &sA[(wm * 32 + i2 * 16) * C_LD + kk], C_LD);
                wmma::load_matrix_sync(bh[i2], &sBh[(wn * 32 + i2 * 16) * C_LD + kk], C_LD);
            }
#pragma unroll
            for (int i2 = 0; i2 < 2; i2++)
#pragma unroll
                for (int j2 = 0; j2 < 2; j2++)
                    wmma::mma_sync(acc[i2][j2], a[i2], bh[j2], acc[i2][j2]);
            wmma::fragment<wmma::matrix_b, 16, 16, 16, h16, wmma::col_major> bl[2];
#pragma unroll
            for (int i2 = 0; i2 < 2; i2++)
                wmma::load_matrix_sync(bl[i2], &sBl[(wn * 32 + i2 * 16) * C_LD + kk], C_LD);
#pragma unroll
            for (int i2 = 0; i2 < 2; i2++)
#pragma unroll
                for (int j2 = 0; j2 < 2; j2++)
                    wmma::mma_sync(acc[i2][j2], a[i2], bl[j2], acc[i2][j2]);
        }
    }
    __syncthreads();
    float* Cs = (float*)sm;
#pragma unroll
    for (int i2 = 0; i2 < 2; i2++)
#pragma unroll
        for (int j2 = 0; j2 < 2; j2++)
            wmma::store_matrix_sync(&Cs[(wm * 32 + i2 * 16) * 128 + wn * 32 + j2 * 16],
                                    acc[i2][j2], 128, wmma::mem_row_major);
    __syncthreads();
    return Cs;
}

// ------- skew core: 128x64, 8 warps, k-chunk 64, 2-stage, 3-term ------------
__device__ __forceinline__ float* gemm_skew3(
    const h16* __restrict__ Ah, const h16* __restrict__ Al,
    const h16* __restrict__ Bh, const h16* __restrict__ Bl,
    int nch, int n0, char* sm)
{
    const int t = threadIdx.x, w = t >> 5;
    const int wm = w >> 1, wn = w & 1;

    wmma::fragment<wmma::accumulator, 16, 16, 16, float> acc[2][2];
#pragma unroll
    for (int i = 0; i < 2; i++)
#pragma unroll
        for (int j = 0; j < 2; j++) wmma::fill_fragment(acc[i][j], 0.f);

    auto issue = [&](int jc) {
        char* st = sm + (jc & 1) * SK_STG;
        int k0 = jc * 64;
#pragma unroll
        for (int u = 0; u < 14; u++) {
            int seg = t + u * 256;
            if (seg >= 3456) break;
            if (seg < 1152) {
                int row = seg / 9, s = seg - row * 9;
                cp16(st + SK_OAH + row * 144 + s * 16,
                     Ah + (size_t)row * KP2 + k0 + s * 8);
            } else if (seg < 2304) {
                int x = seg - 1152;
                int row = x / 9, s = x - row * 9;
                cp16(st + SK_OAL + row * 144 + s * 16,
                     Al + (size_t)row * KP2 + k0 + s * 8);
            } else if (seg < 2880) {
                int x = seg - 2304;
                int row = x / 9, s = x - row * 9;
                cp16(st + SK_OBH + row * 144 + s * 16,
                     Bh + (size_t)(n0 + row) * KP2 + k0 + s * 8);
            } else {
                int x = seg - 2880;
                int row = x / 9, s = x - row * 9;
                cp16(st + SK_OBL + row * 144 + s * 16,
                     Bl + (size_t)(n0 + row) * KP2 + k0 + s * 8);
            }
        }
        asm volatile("cp.async.commit_group;\n" ::: "memory");
    };

    issue(0);
    for (int i = 0; i < nch; i++) {
        asm volatile("cp.async.wait_group 0;\n" ::: "memory");
        __syncthreads();
        if (i + 1 < nch) issue(i + 1);

        char* st = sm + (i & 1) * SK_STG;
        h16* sAh = (h16*)(st + SK_OAH);
        h16* sAl = (h16*)(st + SK_OAL);
        h16* sBh = (h16*)(st + SK_OBH);
        h16* sBl = (h16*)(st + SK_OBL);
#pragma unroll
        for (int ks = 0; ks < 4; ks++) {
            const int kk = ks * 16;
            wmma::fragment<wmma::matrix_a, 16, 16, 16, h16, wmma::row_major> ah[2], al[2];
            wmma::fragment<wmma::matrix_b, 16, 16, 16, h16, wmma::col_major> bh[2], bl[2];
#pragma unroll
            for (int i2 = 0; i2 < 2; i2++) {
                wmma::load_matrix_sync(ah[i2], &sAh[(wm * 32 + i2 * 16) * C_LD + kk], C_LD);
                wmma::load_matrix_sync(al[i2], &sAl[(wm * 32 + i2 * 16) * C_LD + kk], C_LD);
                wmma::load_matrix_sync(bh[i2], &sBh[(wn * 32 + i2 * 16) * C_LD + kk], C_LD);
                wmma::load_matrix_sync(bl[i2], &sBl[(wn * 32 + i2 * 16) * C_LD + kk], C_LD);
            }
#pragma unroll
            for (int i2 = 0; i2 < 2; i2++)
#pragma unroll
                for (int j2 = 0; j2 < 2; j2++) {
                    wmma::mma_sync(acc[i2][j2], ah[i2], bh[j2], acc[i2][j2]);
                    wmma::mma_sync(acc[i2][j2], ah[i2], bl[j2], acc[i2][j2]);
                    wmma::mma_sync(acc[i2][j2], al[i2], bh[j2], acc[i2][j2]);
                }
        }
    }
    __syncthreads();
    float* Cs = (float*)sm;
#pragma unroll
    for (int i2 = 0; i2 < 2; i2++)
#pragma unroll
        for (int j2 = 0; j2 < 2; j2++)
            wmma::store_matrix_sync(&Cs[(wm * 32 + i2 * 16) * 64 + wn * 32 + j2 * 16],
                                    acc[i2][j2], 64, wmma::mem_row_major);
    __syncthreads();
    return Cs;
}

// ------- step core: 128x32 tile, 8 warps (4x2), k-chunk 128, 2-stage --------
__device__ __forceinline__ float* gemm_stepN32(
    const h16* __restrict__ Ah, const h16* __restrict__ Bh,
    int lda, int ldb, int nch, int n0, char* sm)
{
    const int t = threadIdx.x, w = t >> 5;
    const int wm = w >> 1, wn = w & 1;    // warp tile 32x16

    wmma::fragment<wmma::accumulator, 16, 16, 16, float> acc[2];
    wmma::fill_fragment(acc[0], 0.f);
    wmma::fill_fragment(acc[1], 0.f);

    auto issue = [&](int jc) {
        char* st = sm + (jc & 1) * STG_E;
        int k0 = jc * 128;
#pragma unroll
        for (int u = 0; u < 10; u++) {
            int seg = t + u * 256;
            if (seg < 2048) {
                int row = seg >> 4, s = seg & 15;
                cp16(st + E_OA + row * 272 + s * 16,
                     Ah + (size_t)row * lda + k0 + s * 8);
            } else {
                int x = seg - 2048;
                int row = x >> 4, s = x & 15;
                cp16(st + E_OB + row * 272 + s * 16,
                     Bh + (size_t)(n0 + row) * ldb + k0 + s * 8);
            }
        }
        asm volatile("cp.async.commit_group;\n" ::: "memory");
    };

    issue(0);
    for (int i = 0; i < nch; i++) {
        asm volatile("cp.async.wait_group 0;\n" ::: "memory");
        __syncthreads();
        if (i + 1 < nch) issue(i + 1);

        char* st = sm + (i & 1) * STG_E;
        h16* sA = (h16*)(st + E_OA);
        h16* sB = (h16*)(st + E_OB);
#pragma unroll
        for (int ks = 0; ks < 8; ks++) {
            const int kk = ks * 16;
            wmma::fragment<wmma::matrix_a, 16, 16, 16, h16, wmma::row_major> a[2];
            wmma::fragment<wmma::matrix_b, 16, 16, 16, h16, wmma::col_major> b;
            wmma::load_matrix_sync(a[0], &sA[(wm * 32) * E_LD + kk], E_LD);
            wmma::load_matrix_sync(a[1], &sA[(wm * 32 + 16) * E_LD + kk], E_LD);
            wmma::load_matrix_sync(b, &sB[(wn * 16) * E_LD + kk], E_LD);
            wmma::mma_sync(acc[0], a[0], b, acc[0]);
            wmma::mma_sync(acc[1], a[1], b, acc[1]);
        }
    }
    __syncthreads();
    float* Cs = (float*)sm;
    wmma::store_matrix_sync(&Cs[(wm * 32) * 32 + wn * 16], acc[0], 32,
                            wmma::mem_row_major);
    wmma::store_matrix_sync(&Cs[(wm * 32 + 16) * 32 + wn * 16], acc[1], 32,
                            wmma::mem_row_major);
    __syncthreads();
    return Cs;
}

// ------------------------- conv GEMM -------------------------
__global__ __launch_bounds__(256) void k_conv(const float* __restrict__ convb) {
    extern __shared__ char sm[];
    int m0 = blockIdx.x * 128, n0 = blockIdx.y * 64;
    float* Cs = gemm_conv(g_convw_h, g_feat_hi, g_feat_lo,
                          FEATD, FEATD, FEATD / 64, m0, n0, sm);
    // fp32 scatter to g_feats (row-major over cols -> contiguous n runs)
    for (int idx = threadIdx.x; idx < 128 * 64; idx += 256) {
        int r = idx >> 6, cc = idx & 63;
        int m = m0 + r, col = n0 + cc;
        int b = col / NN, n = col - b * NN;
        g_feats[(size_t)b * MIDD * NN + (5 + m) * NN + n] = Cs[idx] + convb[m];
    }
    // h16 split to feats^T (col-major traversal -> m-contiguous writes)
    for (int idx = threadIdx.x; idx < 128 * 64; idx += 256) {
        int cc = idx >> 7, r = idx & 127;
        int m = m0 + r, col = n0 + cc;
        float v = Cs[r * 64 + cc] + convb[m];
        size_t di = (size_t)col * KP2 + 5 + m;
        split_write(v, &g_ft_hi[di], &g_ft_lo[di]);
    }
}

// ------------------------- skew GEMMs (hx, hy) -------------------------
__global__ __launch_bounds__(256) void k_skew() {
    extern __shared__ char sm[];
    int sel = blockIdx.x;               // 0 = wx, 1 = wy
    int n0 = blockIdx.y * 64;
    const h16* Ah = sel ? g_wy_hi : g_wx_hi;
    const h16* Al = sel ? g_wy_lo : g_wx_lo;
    float* out = sel ? g_hy_all : g_hx_all;
    float* Cs = gemm_skew3(Ah, Al, g_ft_hi, g_ft_lo, KP2 / 64, n0, sm);
    for (int idx = threadIdx.x; idx < 128 * 64; idx += 256) {
        int r = idx >> 6, cc = idx & 63;
        out[(size_t)r * COLS + n0 + cc] = Cs[idx];
    }
}

// ------------------------- input-gate GEMM -------------------------
__global__ __launch_bounds__(512) void k_gin(const float* __restrict__ bih,
                                             const float* __restrict__ bhh) {
    extern __shared__ char sm[];
    int m0 = blockIdx.x * 128, n0 = blockIdx.y * 128;
    float* Cs = gemm_big(g_xh, g_wih_hi, g_wih_lo,
                         KP2, KP2, KP2 / 64, m0, n0, sm);
    for (int idx = threadIdx.x; idx < 128 * 128; idx += 512) {
        int r = idx >> 7, cc = idx & 127;
        int row = m0 + r, col = n0 + cc;
        int orig = (col & 3) * OUTD + (col >> 2);
        g_gates_in[(size_t)row * G4 + col] = Cs[idx] + bih[orig] + bhh[orig];
    }
}

// ------------------------- recurrent step: full-K N32 + fused update --------
__global__ __launch_bounds__(256) void k_step(int s, float* __restrict__ outc) {
    extern __shared__ char sm[];
    const int n0 = blockIdx.x * 32;
    const int t = threadIdx.x;

    const h16* hin = (s & 1) ? g_h1 : g_h0;
    h16* hout = (s & 1) ? g_h0 : g_h1;

    {
        const float* gin = g_gates_in + (size_t)s * BB * G4;
        char* sg = sm + GIN_OFF;
#pragma unroll
        for (int u = 0; u < 4; u++) {
            int seg = t + u * 256;
            int row = seg >> 3, ss = seg & 7;
            cp16(sg + row * 128 + ss * 16,
                 gin + (size_t)row * G4 + n0 + ss * 4);
        }
        asm volatile("cp.async.commit_group;\n" ::: "memory");
    }

    float* Cs = gemm_stepN32(hin, g_whh_h, OUTD, OUTD, OUTD / 128, n0, sm);

    const float* sg = (const float*)(sm + GIN_OFF);
    for (int p = t; p < 1024; p += 256) {
        int b = p >> 3, lu = p & 7;
        const float* cr = &Cs[b * 32 + lu * 4];
        float4 gv = *(const float4*)(sg + b * 32 + lu * 4);
        float ig = cr[0] + gv.x;
        float fg = cr[1] + gv.y;
        float gg = cr[2] + gv.z;
        float og = cr[3] + gv.w;
        float si = 1.f / (1.f + expf(-ig));
        float sf = 1.f / (1.f + expf(-fg));
        float so = 1.f / (1.f + expf(-og));
        int u = (n0 >> 2) + lu;
        int ci = b * OUTD + u;
        float c = sf * g_c[ci] + si * tanhf(gg);
        g_c[ci] = c;
        hout[ci] = __float2half(so * tanhf(c));
        if (outc) outc[ci] = c;
    }
}

// --------------- assignment + mix (skew phase now external) -----------------
__global__ __launch_bounds__(512) void k_sa(const float* __restrict__ b1,
                                            const float* __restrict__ w2,
                                            const float* __restrict__ b2p,
                                            const float* __restrict__ lrp) {
    extern __shared__ float S[];
    int b = blockIdx.x, t = threadIdx.x;
    const float* fb = g_feats + (size_t)b * MIDD * NN;

    // load hx/hy slices [128 h][36 n] for this batch
    for (int p = t; p < HIDD * NN; p += 512) {
        int h = p / NN, i = p - h * NN;
        S[SA_HX + p] = g_hx_all[(size_t)h * COLS + b * NN + i];
        S[SA_HY + p] = g_hy_all[(size_t)h * COLS + b * NN + i];
    }
    if (t < 128) { S[SA_W2 + t] = w2[t]; S[SA_B1 + t] = b1[t]; }
    if (t < 36) S[SA_SA + t] = g_sigatt[b * NN + t];
    __syncthreads();

    float b2v = b2p[0];
    for (int p = t; p < 1296; p += 512) {
        int i = p / 36, j = p - i * 36;
        float s = 0.f;
#pragma unroll 8
        for (int h = 0; h < HIDD; h++) {
            float v = S[SA_HX + h * NN + i] + S[SA_HY + h * NN + j] + S[SA_B1 + h];
            s += S[SA_W2 + h] * fmaxf(v, 0.f);
        }
        S[SA_OUT + p] = s + b2v;
    }
    __syncthreads();
    for (int p = t; p < 1296; p += 512) {
        int i = p / 36, j = p - i * 36;
        S[SA_CS + p] = S[SA_OUT + p] - S[SA_OUT + j * 36 + i];
        S[SA_LG + p] = 0.f;
    }
    __syncthreads();

    float lrabs = fabsf(lrp[0]);
    for (int it = 0; it < 3; it++) {
        if (t < 36) {
            float mx = -1e30f;
            for (int j = 0; j < 36; j++) mx = fmaxf(mx, S[SA_LG + t * 36 + j]);
            float sum = 0.f;
            for (int j = 0; j < 36; j++) {
                float e = expf(S[SA_LG + t * 36 + j] - mx);
                S[SA_PS + t * 36 + j] = e;
                sum += e;
            }
            float inv = 1.f / sum;
            for (int j = 0; j < 36; j++) S[SA_PS + t * 36 + j] *= inv;
        }
        __syncthreads();
        if (t < 36) {
            int l = t;
            float tot = 0.f;
            for (int i = 0; i < 36; i++) tot += S[SA_PS + i * 36 + l];
            float run = 0.f;
            for (int i = 0; i < 36; i++) {
                float p = S[SA_PS + i * 36 + l];
                run += p;
                S[SA_DS + i * 36 + l] = tot - 2.f * run + p;
            }
        }
        __syncthreads();
        for (int p = t; p < 1296; p += 512) {
            int i = p / 36, j = p - i * 36;
            float gsum = 0.f;
#pragma unroll
            for (int l = 0; l < 36; l++)
                gsum += S[SA_DS + i * 36 + l] * S[SA_CS + j * 36 + l];
            S[SA_LG + p] -= lrabs * gsum;
        }
        __syncthreads();
    }
    if (t < 36) {
        float mx = -1e30f;
        for (int j = 0; j < 36; j++) mx = fmaxf(mx, S[SA_LG + t * 36 + j]);
        float sum = 0.f;
        for (int j = 0; j < 36; j++) {
            float e = expf(S[SA_LG + t * 36 + j] - mx);
            S[SA_PS + t * 36 + j] = e;
            sum += e;
        }
        float inv = 1.f / sum;
        for (int j = 0; j < 36; j++) S[SA_PS + t * 36 + j] *= inv;
    }
    __syncthreads();

    for (int p = t; p < MIDD * NN; p += 512) {
        int c = p / 36, i = p - c * 36;
        float s = 0.f;
#pragma unroll
        for (int l = 0; l < 36; l++)
            s += fb[c * 36 + l] * S[SA_SA + l] * S[SA_PS + i * 36 + l];
        g_xh[((size_t)i * BB + b) * KP2 + c] = __float2half(s);
    }
    for (int p = t; p < (KP2 - MIDD) * NN; p += 512) {
        int c = MIDD + p / 36, i = p % 36;
        g_xh[((size_t)i * BB + b) * KP2 + c] = __float2half(0.f);
    }
}

// ------------------------- launch -------------------------
extern "C" void kernel_launch(void* const* d_in, const int* in_sizes, int n_in,
                              void* d_out, int out_size) {
    const float* boxes     = (const float*)d_in[0];
    const float* attention = (const float*)d_in[1];
    const float* features  = (const float*)d_in[2];
    const float* conv_w    = (const float*)d_in[3];
    const float* conv_b    = (const float*)d_in[4];
    const float* skew_wx   = (const float*)d_in[5];
    const float* skew_wy   = (const float*)d_in[6];
    const float* skew_b1   = (const float*)d_in[7];
    const float* skew_w2   = (const float*)d_in[8];
    const float* skew_b2   = (const float*)d_in[9];
    const float* w_ih      = (const float*)d_in[10];
    const float* w_hh      = (const float*)d_in[11];
    const float* b_ih      = (const float*)d_in[12];
    const float* b_hh      = (const float*)d_in[13];
    const float* lr        = (const float*)d_in[14];

    static int attr_done = 0;
    if (!attr_done) {
        cudaFuncSetAttribute(k_conv, cudaFuncAttributeMaxDynamicSharedMemorySize, DYN_CONV);
        cudaFuncSetAttribute(k_gin,  cudaFuncAttributeMaxDynamicSharedMemorySize, DYN_GIN);
        cudaFuncSetAttribute(k_skew, cudaFuncAttributeMaxDynamicSharedMemorySize, DYN_SKEW);
        cudaFuncSetAttribute(k_step, cudaFuncAttributeMaxDynamicSharedMemorySize, DYN_STEP);
        cudaFuncSetAttribute(k_sa,   cudaFuncAttributeMaxDynamicSharedMemorySize, SA_DYN);
        attr_done = 1;
    }

    k_init<<<(BB * OUTD + 255) / 256, 256>>>(boxes);
    {
        size_t total = PN1 + PN2 + PN3 + PN4 + PN5 + PN6 + PN7;
        k_prep<<<(unsigned)((total + 511) / 512), 512>>>(
            conv_w, w_ih, w_hh, features, boxes, attention, skew_wx, skew_wy);
    }
    k_conv<<<dim3(4, 72), 256, DYN_CONV>>>(conv_b);
    k_skew<<<dim3(2, 72), 256, DYN_SKEW>>>();
    k_sa<<<BB, 512, SA_DYN>>>(skew_b1, skew_w2, skew_b2, lr);
    k_gin<<<dim3(36, 32), 512, DYN_GIN>>>(b_ih, b_hh);

    for (int s = 0; s < TSTEPS; s++) {
        k_step<<<128, 256, DYN_STEP>>>(s, s == TSTEPS - 1 ? (float*)d_out : nullptr);
    }
}

// round 17
// speedup vs baseline: 1.1505x; 1.0230x over previous
#include <cuda_runtime.h>
#include <cuda_fp16.h>
#include <mma.h>
#include <cstdint>

using namespace nvcuda;
typedef __half h16;

#define BB   128
#define NN   36
#define FEATD 2048
#define MIDD 517
#define HIDD 128
#define OUTD 1024
#define G4   4096
#define KP2  576
#define COLS 4608          // BB*NN
#define TSTEPS 36

#define C_LD   72                        // smem row stride in h16 (144B)

// ---- conv core: 128x64 tile, 8 warps, k-chunk 64, 2-stage, NT2 ----
#define C_OA   0
#define C_OBH  18432
#define C_OBL  27648
#define STGC   36864
#define DYN_CONV (2 * STGC)              // 73728

// ---- gin core: 256x128 tile, 16 warps (4x4), k-chunk 64, 2-stage ----
#define G_OA   0                         // A: 256*144 = 36864
#define G_OBH  36864                     // Bh: 128*144 = 18432
#define G_OBL  55296                     // Bl: 18432
#define G_STG  73728
#define DYN_GIN (2 * G_STG)              // 147456

// ---- skew core: 128x64 tile, 8 warps, k-chunk 64, 2-stage, 3-term ----
#define SK_OAH 0
#define SK_OAL 18432
#define SK_OBH 36864
#define SK_OBL 46080
#define SK_STG 55296
#define DYN_SKEW (2 * SK_STG)            // 110592

// ---- step core: 128x32 tile, 8 warps, k-chunk 128, 2-stage, full-K ----
#define E_LD   136                       // row stride in h16 (272B)
#define E_OA   0                         // A: 128*272 = 34816
#define E_OB   34816                     // B: 32*272 = 8704
#define STG_E  43520
#define GIN_OFF (2 * STG_E)              // gates_in tile: 128*32*4 = 16384
#define CST_OFF (2 * STG_E + 16384)      // c tile: 128*8*4 = 4096
#define DYN_STEP (2 * STG_E + 16384 + 4096)  // 107520

// ---- k_sa smem layout (floats) ----
#define SA_HX   0
#define SA_HY   4608
#define SA_OUT  9216
#define SA_CS   10512
#define SA_LG   11808
#define SA_PS   13104
#define SA_DS   14400
#define SA_SA   15696
#define SA_W2   15732
#define SA_B1   15860
#define SA_TOT  15988
#define SA_DYN  (SA_TOT * 4)             // 63952

// ------------------------- scratch -------------------------
__device__ float g_scale[BB];
__device__ float g_sigatt[BB * NN];
__device__ float g_feats[BB * MIDD * NN];                 // [b][m][n] fp32 (mix)

__device__ __align__(16) h16 g_feat_hi[(size_t)BB * NN * FEATD];
__device__ __align__(16) h16 g_feat_lo[(size_t)BB * NN * FEATD];
__device__ __align__(16) h16 g_convw_h[512 * FEATD];
__device__ __align__(16) h16 g_ft_hi[(size_t)COLS * KP2];   // feats^T [col][m]
__device__ __align__(16) h16 g_ft_lo[(size_t)COLS * KP2];
__device__ __align__(16) h16 g_wx_hi[HIDD * KP2];
__device__ __align__(16) h16 g_wx_lo[HIDD * KP2];
__device__ __align__(16) h16 g_wy_hi[HIDD * KP2];
__device__ __align__(16) h16 g_wy_lo[HIDD * KP2];
__device__ float g_hx_all[(size_t)HIDD * COLS];             // [h][col]
__device__ float g_hy_all[(size_t)HIDD * COLS];
__device__ __align__(16) h16 g_wih_hi[(size_t)G4 * KP2];    // col = u*4+g
__device__ __align__(16) h16 g_wih_lo[(size_t)G4 * KP2];
__device__ __align__(16) h16 g_whh_h[(size_t)G4 * OUTD];    // reordered
__device__ __align__(16) h16 g_xh[(size_t)TSTEPS * BB * KP2];
__device__ float g_gates_in[(size_t)TSTEPS * BB * G4];      // reordered cols
__device__ __align__(16) h16 g_h0[BB * OUTD];
__device__ __align__(16) h16 g_h1[BB * OUTD];
__device__ float g_c[BB * OUTD];

// ------------------------- helpers -------------------------
__device__ __forceinline__ void split_write(float v, h16* hi, h16* lo) {
    h16 h = __float2half(v);
    *hi = h;
    *lo = __float2half(v - __half2float(h));
}

__device__ __forceinline__ void cp16(void* dst, const void* src) {
    unsigned d = (unsigned)__cvta_generic_to_shared(dst);
    asm volatile("cp.async.ca.shared.global [%0], [%1], 16;\n" ::"r"(d), "l"(src));
}

// ------------------------- init (scale + state) -------------------------
__global__ void k_init(const float* __restrict__ boxes) {
    int idx = blockIdx.x * blockDim.x + threadIdx.x;
    if (idx < BB) {
        const float* p = boxes + (size_t)idx * 4 * NN;
        float m = -1e30f;
        for (int i = 0; i < 4 * NN; i++) m = fmaxf(m, p[i]);
        g_scale[idx] = m;
    }
    if (idx < BB * OUTD) {
        g_h0[idx] = __float2half(0.f);
        g_c[idx] = 0.f;
    }
}

// ---------------- fused prep (weights + features + head + pads) -------------
#define PN1 ((size_t)512 * FEATD)
#define PN2 ((size_t)G4 * KP2)
#define PN3 ((size_t)G4 * OUTD)
#define PN4 ((size_t)BB * NN * FEATD)
#define PN5 ((size_t)BB * NN)
#define PN6 ((size_t)2 * HIDD * KP2)
#define PN7 ((size_t)COLS * (KP2 - MIDD))
__global__ void k_prep(const float* __restrict__ cw, const float* __restrict__ wih,
                       const float* __restrict__ whh, const float* __restrict__ feat,
                       const float* __restrict__ boxes, const float* __restrict__ att,
                       const float* __restrict__ wx, const float* __restrict__ wy) {
    size_t idx = (size_t)blockIdx.x * blockDim.x + threadIdx.x;
    if (idx < PN1) {
        g_convw_h[idx] = __float2half(cw[idx]);
    } else if (idx < PN1 + PN2) {
        size_t i = idx - PN1;
        int cr = (int)(i / KP2), k = (int)(i - (size_t)cr * KP2);
        int u = cr >> 2, g = cr & 3;
        float v = (k < MIDD) ? wih[(size_t)(g * OUTD + u) * MIDD + k] : 0.f;
        split_write(v, &g_wih_hi[i], &g_wih_lo[i]);
    } else if (idx < PN1 + PN2 + PN3) {
        size_t i = idx - PN1 - PN2;
        int cr = (int)(i / OUTD), k = (int)(i - (size_t)cr * OUTD);
        int u = cr >> 2, g = cr & 3;
        g_whh_h[i] = __float2half(whh[(size_t)(g * OUTD + u) * OUTD + k]);
    } else if (idx < PN1 + PN2 + PN3 + PN4) {
        size_t i = idx - PN1 - PN2 - PN3;
        split_write(feat[i], &g_feat_hi[i], &g_feat_lo[i]);
    } else if (idx < PN1 + PN2 + PN3 + PN4 + PN5) {
        int i = (int)(idx - PN1 - PN2 - PN3 - PN4);   // i == col
        int b = i / NN, n = i - b * NN;
        float inv = 1.f / g_scale[b];
        for (int r = 0; r < 4; r++) {
            float v = boxes[(size_t)b * 4 * NN + r * NN + n] * inv;
            g_feats[(size_t)b * MIDD * NN + r * NN + n] = v;
            split_write(v, &g_ft_hi[(size_t)i * KP2 + r], &g_ft_lo[(size_t)i * KP2 + r]);
        }
        float a = att[i];
        g_feats[(size_t)b * MIDD * NN + 4 * NN + n] = a;
        split_write(a, &g_ft_hi[(size_t)i * KP2 + 4], &g_ft_lo[(size_t)i * KP2 + 4]);
        g_sigatt[i] = 1.f / (1.f + expf(-a));
    } else if (idx < PN1 + PN2 + PN3 + PN4 + PN5 + PN6) {
        size_t i = idx - PN1 - PN2 - PN3 - PN4 - PN5;
        int sel = (int)(i / (HIDD * KP2));
        int j = (int)(i - (size_t)sel * HIDD * KP2);
        int h = j / KP2, k = j - h * KP2;
        const float* src = sel ? wy : wx;
        float v = (k < MIDD) ? src[(size_t)h * MIDD + k] : 0.f;
        if (sel) split_write(v, &g_wy_hi[j], &g_wy_lo[j]);
        else     split_write(v, &g_wx_hi[j], &g_wx_lo[j]);
    } else if (idx < PN1 + PN2 + PN3 + PN4 + PN5 + PN6 + PN7) {
        size_t i = idx - PN1 - PN2 - PN3 - PN4 - PN5 - PN6;
        int col = (int)(i / (KP2 - MIDD));
        int m = MIDD + (int)(i - (size_t)col * (KP2 - MIDD));
        g_ft_hi[(size_t)col * KP2 + m] = __float2half(0.f);
        g_ft_lo[(size_t)col * KP2 + m] = __float2half(0.f);
    }
}

// -------------- conv core: 128x64, 8 warps, k-chunk 64, 2-stage, NT2 --------
__device__ __forceinline__ float* gemm_conv(
    const h16* __restrict__ Ah,
    const h16* __restrict__ Bh, const h16* __restrict__ Bl,
    int lda, int ldb, int nch, int m0, int n0, char* sm)
{
    const int t = threadIdx.x, w = t >> 5;
    const int wm = w >> 1, wn = w & 1;

    wmma::fragment<wmma::accumulator, 16, 16, 16, float> acc[2][2];
#pragma unroll
    for (int i = 0; i < 2; i++)
#pragma unroll
        for (int j = 0; j < 2; j++) wmma::fill_fragment(acc[i][j], 0.f);

    auto issue = [&](int jc) {
        char* st = sm + (jc & 1) * STGC;
        int k0 = jc * 64;
#pragma unroll
        for (int u = 0; u < 8; u++) {
            int seg = t + u * 256;
            if (seg < 1024) {
                int row = seg >> 3, s = seg & 7;
                cp16(st + C_OA + row * 144 + s * 16,
                     Ah + (size_t)(m0 + row) * lda + k0 + s * 8);
            } else if (seg < 1536) {
                int x = seg - 1024;
                int row = x >> 3, s = x & 7;
                cp16(st + C_OBH + row * 144 + s * 16,
                     Bh + (size_t)(n0 + row) * ldb + k0 + s * 8);
            } else {
                int x = seg - 1536;
                int row = x >> 3, s = x & 7;
                cp16(st + C_OBL + row * 144 + s * 16,
                     Bl + (size_t)(n0 + row) * ldb + k0 + s * 8);
            }
        }
        asm volatile("cp.async.commit_group;\n" ::: "memory");
    };

    issue(0);
    for (int i = 0; i < nch; i++) {
        asm volatile("cp.async.wait_group 0;\n" ::: "memory");
        __syncthreads();
        if (i + 1 < nch) issue(i + 1);

        char* st = sm + (i & 1) * STGC;
        h16* sA = (h16*)(st + C_OA);
        h16* sBh = (h16*)(st + C_OBH);
        h16* sBl = (h16*)(st + C_OBL);
#pragma unroll
        for (int ks = 0; ks < 4; ks++) {
            const int kk = ks * 16;
            wmma::fragment<wmma::matrix_a, 16, 16, 16, h16, wmma::row_major> a[2];
            wmma::fragment<wmma::matrix_b, 16, 16, 16, h16, wmma::col_major> bh[2];
#pragma unroll
            for (int i2 = 0; i2 < 2; i2++) {
                wmma::load_matrix_sync(a[i2], &sA[(wm * 32 + i2 * 16) * C_LD + kk], C_LD);
                wmma::load_matrix_sync(bh[i2], &sBh[(wn * 32 + i2 * 16) * C_LD + kk], C_LD);
            }
#pragma unroll
            for (int i2 = 0; i2 < 2; i2++)
#pragma unroll
                for (int j2 = 0; j2 < 2; j2++)
                    wmma::mma_sync(acc[i2][j2], a[i2], bh[j2], acc[i2][j2]);
            wmma::fragment<wmma::matrix_b, 16, 16, 16, h16, wmma::col_major> bl[2];
#pragma unroll
            for (int i2 = 0; i2 < 2; i2++)
                wmma::load_matrix_sync(bl[i2], &sBl[(wn * 32 + i2 * 16) * C_LD + kk], C_LD);
#pragma unroll
            for (int i2 = 0; i2 < 2; i2++)
#pragma unroll
                for (int j2 = 0; j2 < 2; j2++)
                    wmma::mma_sync(acc[i2][j2], a[i2], bl[j2], acc[i2][j2]);
        }
    }
    __syncthreads();
    float* Cs = (float*)sm;
#pragma unroll
    for (int i2 = 0; i2 < 2; i2++)
#pragma unroll
        for (int j2 = 0; j2 < 2; j2++)
            wmma::store_matrix_sync(&Cs[(wm * 32 + i2 * 16) * 64 + wn * 32 + j2 * 16],
                                    acc[i2][j2], 64, wmma::mem_row_major);
    __syncthreads();
    return Cs;
}

// ------- gin core: 256x128, 16 warps (4x4), k-chunk 64, 2-stage, NT2 --------
__device__ __forceinline__ float* gemm_gin256(
    const h16* __restrict__ Ah,
    const h16* __restrict__ Bh, const h16* __restrict__ Bl,
    int nch, int m0, int n0, char* sm)
{
    const int t = threadIdx.x, w = t >> 5;
    const int wm = w >> 2, wn = w & 3;     // warp tile 64x32

    wmma::fragment<wmma::accumulator, 16, 16, 16, float> acc[4][2];
#pragma unroll
    for (int i = 0; i < 4; i++)
#pragma unroll
        for (int j = 0; j < 2; j++) wmma::fill_fragment(acc[i][j], 0.f);

    auto issue = [&](int jc) {
        char* st = sm + (jc & 1) * G_STG;
        int k0 = jc * 64;
        // 4608 segs: A 2304 | Bh 1152 | Bl 1152 ; 9 iters x 512
#pragma unroll
        for (int u = 0; u < 9; u++) {
            int seg = t + u * 512;
            if (seg < 2304) {
                int row = seg / 9, s = seg - row * 9;
                cp16(st + G_OA + row * 144 + s * 16,
                     Ah + (size_t)(m0 + row) * KP2 + k0 + s * 8);
            } else if (seg < 3456) {
                int x = seg - 2304;
                int row = x / 9, s = x - row * 9;
                cp16(st + G_OBH + row * 144 + s * 16,
                     Bh + (size_t)(n0 + row) * KP2 + k0 + s * 8);
            } else {
                int x = seg - 3456;
                int row = x / 9, s = x - row * 9;
                cp16(st + G_OBL + row * 144 + s * 16,
                     Bl + (size_t)(n0 + row) * KP2 + k0 + s * 8);
            }
        }
        asm volatile("cp.async.commit_group;\n" ::: "memory");
    };

    issue(0);
    for (int i = 0; i < nch; i++) {
        asm volatile("cp.async.wait_group 0;\n" ::: "memory");
        __syncthreads();
        if (i + 1 < nch) issue(i + 1);

        char* st = sm + (i & 1) * G_STG;
        h16* sA = (h16*)(st + G_OA);
        h16* sBh = (h16*)(st + G_OBH);
        h16* sBl = (h16*)(st + G_OBL);
#pragma unroll
        for (int ks = 0; ks < 4; ks++) {
            const int kk = ks * 16;
            wmma::fragment<wmma::matrix_a, 16, 16, 16, h16, wmma::row_major> a[4];
            wmma::fragment<wmma::matrix_b, 16, 16, 16, h16, wmma::col_major> bh[2];
#pragma unroll
            for (int i2 = 0; i2 < 4; i2++)
                wmma::load_matrix_sync(a[i2], &sA[(wm * 64 + i2 * 16) * C_LD + kk], C_LD);
#pragma unroll
            for (int j2 = 0; j2 < 2; j2++)
                wmma::load_matrix_sync(bh[j2], &sBh[(wn * 32 + j2 * 16) * C_LD + kk], C_LD);
#pragma unroll
            for (int i2 = 0; i2 < 4; i2++)
#pragma unroll
                for (int j2 = 0; j2 < 2; j2++)
                    wmma::mma_sync(acc[i2][j2], a[i2], bh[j2], acc[i2][j2]);
            wmma::fragment<wmma::matrix_b, 16, 16, 16, h16, wmma::col_major> bl[2];
#pragma unroll
            for (int j2 = 0; j2 < 2; j2++)
                wmma::load_matrix_sync(bl[j2], &sBl[(wn * 32 + j2 * 16) * C_LD + kk], C_LD);
#pragma unroll
            for (int i2 = 0; i2 < 4; i2++)
#pragma unroll
                for (int j2 = 0; j2 < 2; j2++)
                    wmma::mma_sync(acc[i2][j2], a[i2], bl[j2], acc[i2][j2]);
        }
    }
    __syncthreads();
    float* Cs = (float*)sm;   // 256*128*4 = 128KB <= 147KB stages
#pragma unroll
    for (int i2 = 0; i2 < 4; i2++)
#pragma unroll
        for (int j2 = 0; j2 < 2; j2++)
            wmma::store_matrix_sync(&Cs[(wm * 64 + i2 * 16) * 128 + wn * 32 + j2 * 16],
                                    acc[i2][j2], 128, wmma::mem_row_major);
    __syncthreads();
    return Cs;
}

// ------- skew core: 128x64, 8 warps, k-chunk 64, 2-stage, 3-term ------------
__device__ __forceinline__ float* gemm_skew3(
    const h16* __restrict__ Ah, const h16* __restrict__ Al,
    const h16* __restrict__ Bh, const h16* __restrict__ Bl,
    int nch, int n0, char* sm)
{
    const int t = threadIdx.x, w = t >> 5;
    const int wm = w >> 1, wn = w & 1;

    wmma::fragment<wmma::accumulator, 16, 16, 16, float> acc[2][2];
#pragma unroll
    for (int i = 0; i < 2; i++)
#pragma unroll
        for (int j = 0; j < 2; j++) wmma::fill_fragment(acc[i][j], 0.f);

    auto issue = [&](int jc) {
        char* st = sm + (jc & 1) * SK_STG;
        int k0 = jc * 64;
#pragma unroll
        for (int u = 0; u < 14; u++) {
            int seg = t + u * 256;
            if (seg >= 3456) break;
            if (seg < 1152) {
                int row = seg / 9, s = seg - row * 9;
                cp16(st + SK_OAH + row * 144 + s * 16,
                     Ah + (size_t)row * KP2 + k0 + s * 8);
            } else if (seg < 2304) {
                int x = seg - 1152;
                int row = x / 9, s = x - row * 9;
                cp16(st + SK_OAL + row * 144 + s * 16,
                     Al + (size_t)row * KP2 + k0 + s * 8);
            } else if (seg < 2880) {
                int x = seg - 2304;
                int row = x / 9, s = x - row * 9;
                cp16(st + SK_OBH + row * 144 + s * 16,
                     Bh + (size_t)(n0 + row) * KP2 + k0 + s * 8);
            } else {
                int x = seg - 2880;
                int row = x / 9, s = x - row * 9;
                cp16(st + SK_OBL + row * 144 + s * 16,
                     Bl + (size_t)(n0 + row) * KP2 + k0 + s * 8);
            }
        }
        asm volatile("cp.async.commit_group;\n" ::: "memory");
    };

    issue(0);
    for (int i = 0; i < nch; i++) {
        asm volatile("cp.async.wait_group 0;\n" ::: "memory");
        __syncthreads();
        if (i + 1 < nch) issue(i + 1);

        char* st = sm + (i & 1) * SK_STG;
        h16* sAh = (h16*)(st + SK_OAH);
        h16* sAl = (h16*)(st + SK_OAL);
        h16* sBh = (h16*)(st + SK_OBH);
        h16* sBl = (h16*)(st + SK_OBL);
#pragma unroll
        for (int ks = 0; ks < 4; ks++) {
            const int kk = ks * 16;
            wmma::fragment<wmma::matrix_a, 16, 16, 16, h16, wmma::row_major> ah[2], al[2];
            wmma::fragment<wmma::matrix_b, 16, 16, 16, h16, wmma::col_major> bh[2], bl[2];
#pragma unroll
            for (int i2 = 0; i2 < 2; i2++) {
                wmma::load_matrix_sync(ah[i2], &sAh[(wm * 32 + i2 * 16) * C_LD + kk], C_LD);
                wmma::load_matrix_sync(al[i2], &sAl[(wm * 32 + i2 * 16) * C_LD + kk], C_LD);
                wmma::load_matrix_sync(bh[i2], &sBh[(wn * 32 + i2 * 16) * C_LD + kk], C_LD);
                wmma::load_matrix_sync(bl[i2], &sBl[(wn * 32 + i2 * 16) * C_LD + kk], C_LD);
            }
#pragma unroll
            for (int i2 = 0; i2 < 2; i2++)
#pragma unroll
                for (int j2 = 0; j2 < 2; j2++) {
                    wmma::mma_sync(acc[i2][j2], ah[i2], bh[j2], acc[i2][j2]);
                    wmma::mma_sync(acc[i2][j2], ah[i2], bl[j2], acc[i2][j2]);
                    wmma::mma_sync(acc[i2][j2], al[i2], bh[j2], acc[i2][j2]);
                }
        }
    }
    __syncthreads();
    float* Cs = (float*)sm;
#pragma unroll
    for (int i2 = 0; i2 < 2; i2++)
#pragma unroll
        for (int j2 = 0; j2 < 2; j2++)
            wmma::store_matrix_sync(&Cs[(wm * 32 + i2 * 16) * 64 + wn * 32 + j2 * 16],
                                    acc[i2][j2], 64, wmma::mem_row_major);
    __syncthreads();
    return Cs;
}

// ------- step core: 128x32 tile, 8 warps (4x2), k-chunk 128, 2-stage --------
__device__ __forceinline__ float* gemm_stepN32(
    const h16* __restrict__ Ah, const h16* __restrict__ Bh,
    int lda, int ldb, int nch, int n0, char* sm)
{
    const int t = threadIdx.x, w = t >> 5;
    const int wm = w >> 1, wn = w & 1;    // warp tile 32x16

    wmma::fragment<wmma::accumulator, 16, 16, 16, float> acc[2];
    wmma::fill_fragment(acc[0], 0.f);
    wmma::fill_fragment(acc[1], 0.f);

    auto issue = [&](int jc) {
        char* st = sm + (jc & 1) * STG_E;
        int k0 = jc * 128;
#pragma unroll
        for (int u = 0; u < 10; u++) {
            int seg = t + u * 256;
            if (seg < 2048) {
                int row = seg >> 4, s = seg & 15;
                cp16(st + E_OA + row * 272 + s * 16,
                     Ah + (size_t)row * lda + k0 + s * 8);
            } else {
                int x = seg - 2048;
                int row = x >> 4, s = x & 15;
                cp16(st + E_OB + row * 272 + s * 16,
                     Bh + (size_t)(n0 + row) * ldb + k0 + s * 8);
            }
        }
        asm volatile("cp.async.commit_group;\n" ::: "memory");
    };

    issue(0);
    for (int i = 0; i < nch; i++) {
        asm volatile("cp.async.wait_group 0;\n" ::: "memory");
        __syncthreads();
        if (i + 1 < nch) issue(i + 1);

        char* st = sm + (i & 1) * STG_E;
        h16* sA = (h16*)(st + E_OA);
        h16* sB = (h16*)(st + E_OB);
#pragma unroll
        for (int ks = 0; ks < 8; ks++) {
            const int kk = ks * 16;
            wmma::fragment<wmma::matrix_a, 16, 16, 16, h16, wmma::row_major> a[2];
            wmma::fragment<wmma::matrix_b, 16, 16, 16, h16, wmma::col_major> b;
            wmma::load_matrix_sync(a[0], &sA[(wm * 32) * E_LD + kk], E_LD);
            wmma::load_matrix_sync(a[1], &sA[(wm * 32 + 16) * E_LD + kk], E_LD);
            wmma::load_matrix_sync(b, &sB[(wn * 16) * E_LD + kk], E_LD);
            wmma::mma_sync(acc[0], a[0], b, acc[0]);
            wmma::mma_sync(acc[1], a[1], b, acc[1]);
        }
    }
    __syncthreads();
    float* Cs = (float*)sm;
    wmma::store_matrix_sync(&Cs[(wm * 32) * 32 + wn * 16], acc[0], 32,
                            wmma::mem_row_major);
    wmma::store_matrix_sync(&Cs[(wm * 32 + 16) * 32 + wn * 16], acc[1], 32,
                            wmma::mem_row_major);
    __syncthreads();
    return Cs;
}

// ------------------------- conv GEMM -------------------------
__global__ __launch_bounds__(256) void k_conv(const float* __restrict__ convb) {
    extern __shared__ char sm[];
    int m0 = blockIdx.x * 128, n0 = blockIdx.y * 64;
    float* Cs = gemm_conv(g_convw_h, g_feat_hi, g_feat_lo,
                          FEATD, FEATD, FEATD / 64, m0, n0, sm);
    for (int idx = threadIdx.x; idx < 128 * 64; idx += 256) {
        int r = idx >> 6, cc = idx & 63;
        int m = m0 + r, col = n0 + cc;
        int b = col / NN, n = col - b * NN;
        g_feats[(size_t)b * MIDD * NN + (5 + m) * NN + n] = Cs[idx] + convb[m];
    }
    for (int idx = threadIdx.x; idx < 128 * 64; idx += 256) {
        int cc = idx >> 7, r = idx & 127;
        int m = m0 + r, col = n0 + cc;
        float v = Cs[r * 64 + cc] + convb[m];
        size_t di = (size_t)col * KP2 + 5 + m;
        split_write(v, &g_ft_hi[di], &g_ft_lo[di]);
    }
}

// ------------------------- skew GEMMs (hx, hy) -------------------------
__global__ __launch_bounds__(256) void k_skew() {
    extern __shared__ char sm[];
    int sel = blockIdx.x;
    int n0 = blockIdx.y * 64;
    const h16* Ah = sel ? g_wy_hi : g_wx_hi;
    const h16* Al = sel ? g_wy_lo : g_wx_lo;
    float* out = sel ? g_hy_all : g_hx_all;
    float* Cs = gemm_skew3(Ah, Al, g_ft_hi, g_ft_lo, KP2 / 64, n0, sm);
    for (int idx = threadIdx.x; idx < 128 * 64; idx += 256) {
        int r = idx >> 6, cc = idx & 63;
        out[(size_t)r * COLS + n0 + cc] = Cs[idx];
    }
}

// ------------------------- input-gate GEMM -------------------------
__global__ __launch_bounds__(512) void k_gin(const float* __restrict__ bih,
                                             const float* __restrict__ bhh) {
    extern __shared__ char sm[];
    int m0 = blockIdx.x * 256, n0 = blockIdx.y * 128;
    float* Cs = gemm_gin256(g_xh, g_wih_hi, g_wih_lo, KP2 / 64, m0, n0, sm);
    for (int idx = threadIdx.x; idx < 256 * 128; idx += 512) {
        int r = idx >> 7, cc = idx & 127;
        int row = m0 + r, col = n0 + cc;
        int orig = (col & 3) * OUTD + (col >> 2);
        g_gates_in[(size_t)row * G4 + col] = Cs[idx] + bih[orig] + bhh[orig];
    }
}

// ------------------------- recurrent step: full-K N32 + fused update --------
__global__ __launch_bounds__(256) void k_step(int s, float* __restrict__ outc) {
    extern __shared__ char sm[];
    const int n0 = blockIdx.x * 32;
    const int t = threadIdx.x;

    const h16* hin = (s & 1) ? g_h1 : g_h0;
    h16* hout = (s & 1) ? g_h0 : g_h1;

    // prefetch gates_in tile [128 x 32] fp32 and c tile [128 x 8] fp32
    {
        const float* gin = g_gates_in + (size_t)s * BB * G4;
        char* sg = sm + GIN_OFF;
#pragma unroll
        for (int u = 0; u < 4; u++) {
            int seg = t + u * 256;
            int row = seg >> 3, ss = seg & 7;
            cp16(sg + row * 128 + ss * 16,
                 gin + (size_t)row * G4 + n0 + ss * 4);
        }
        char* sc = sm + CST_OFF;
        {
            int row = t >> 1, ss = t & 1;   // 256 segs: 128 rows x 2
            cp16(sc + row * 32 + ss * 16,
                 g_c + (size_t)row * OUTD + (n0 >> 2) + ss * 4);
        }
        asm volatile("cp.async.commit_group;\n" ::: "memory");
    }

    float* Cs = gemm_stepN32(hin, g_whh_h, OUTD, OUTD, OUTD / 128, n0, sm);

    const float* sg = (const float*)(sm + GIN_OFF);
    const float* sc = (const float*)(sm + CST_OFF);
    for (int p = t; p < 1024; p += 256) {
        int b = p >> 3, lu = p & 7;
        const float* cr = &Cs[b * 32 + lu * 4];
        float4 gv = *(const float4*)(sg + b * 32 + lu * 4);
        float ig = cr[0] + gv.x;
        float fg = cr[1] + gv.y;
        float gg = cr[2] + gv.z;
        float og = cr[3] + gv.w;
        float si = 1.f / (1.f + expf(-ig));
        float sf = 1.f / (1.f + expf(-fg));
        float so = 1.f / (1.f + expf(-og));
        int u = (n0 >> 2) + lu;
        int ci = b * OUTD + u;
        float c = sf * sc[b * 8 + lu] + si * tanhf(gg);
        g_c[ci] = c;
        hout[ci] = __float2half(so * tanhf(c));
        if (outc) outc[ci] = c;
    }
}

// --------------- assignment + mix (skew phase external) ---------------------
__global__ __launch_bounds__(512) void k_sa(const float* __restrict__ b1,
                                            const float* __restrict__ w2,
                                            const float* __restrict__ b2p,
                                            const float* __restrict__ lrp) {
    extern __shared__ float S[];
    int b = blockIdx.x, t = threadIdx.x;
    const float* fb = g_feats + (size_t)b * MIDD * NN;

    for (int p = t; p < HIDD * NN; p += 512) {
        int h = p / NN, i = p - h * NN;
        S[SA_HX + p] = g_hx_all[(size_t)h * COLS + b * NN + i];
        S[SA_HY + p] = g_hy_all[(size_t)h * COLS + b * NN + i];
    }
    if (t < 128) { S[SA_W2 + t] = w2[t]; S[SA_B1 + t] = b1[t]; }
    if (t < 36) S[SA_SA + t] = g_sigatt[b * NN + t];
    __syncthreads();

    float b2v = b2p[0];
    for (int p = t; p < 1296; p += 512) {
        int i = p / 36, j = p - i * 36;
        float s = 0.f;
#pragma unroll 8
        for (int h = 0; h < HIDD; h++) {
            float v = S[SA_HX + h * NN + i] + S[SA_HY + h * NN + j] + S[SA_B1 + h];
            s += S[SA_W2 + h] * fmaxf(v, 0.f);
        }
        S[SA_OUT + p] = s + b2v;
    }
    __syncthreads();
    for (int p = t; p < 1296; p += 512) {
        int i = p / 36, j = p - i * 36;
        S[SA_CS + p] = S[SA_OUT + p] - S[SA_OUT + j * 36 + i];
        S[SA_LG + p] = 0.f;
    }
    __syncthreads();

    float lrabs = fabsf(lrp[0]);
    for (int it = 0; it < 3; it++) {
        if (t < 36) {
            float mx = -1e30f;
            for (int j = 0; j < 36; j++) mx = fmaxf(mx, S[SA_LG + t * 36 + j]);
            float sum = 0.f;
            for (int j = 0; j < 36; j++) {
                float e = expf(S[SA_LG + t * 36 + j] - mx);
                S[SA_PS + t * 36 + j] = e;
                sum += e;
            }
            float inv = 1.f / sum;
            for (int j = 0; j < 36; j++) S[SA_PS + t * 36 + j] *= inv;
        }
        __syncthreads();
        if (t < 36) {
            int l = t;
            float tot = 0.f;
            for (int i = 0; i < 36; i++) tot += S[SA_PS + i * 36 + l];
            float run = 0.f;
            for (int i = 0; i < 36; i++) {
                float p = S[SA_PS + i * 36 + l];
                run += p;
                S[SA_DS + i * 36 + l] = tot - 2.f * run + p;
            }
        }
        __syncthreads();
        for (int p = t; p < 1296; p += 512) {
            int i = p / 36, j = p - i * 36;
            float gsum = 0.f;
#pragma unroll
            for (int l = 0; l < 36; l++)
                gsum += S[SA_DS + i * 36 + l] * S[SA_CS + j * 36 + l];
            S[SA_LG + p] -= lrabs * gsum;
        }
        __syncthreads();
    }
    if (t < 36) {
        float mx = -1e30f;
        for (int j = 0; j < 36; j++) mx = fmaxf(mx, S[SA_LG + t * 36 + j]);
        float sum = 0.f;
        for (int j = 0; j < 36; j++) {
            float e = expf(S[SA_LG + t * 36 + j] - mx);
            S[SA_PS + t * 36 + j] = e;
            sum += e;
        }
        float inv = 1.f / sum;
        for (int j = 0; j < 36; j++) S[SA_PS + t * 36 + j] *= inv;
    }
    __syncthreads();

    for (int p = t; p < MIDD * NN; p += 512) {
        int c = p / 36, i = p - c * 36;
        float s = 0.f;
#pragma unroll
        for (int l = 0; l < 36; l++)
            s += fb[c * 36 + l] * S[SA_SA + l] * S[SA_PS + i * 36 + l];
        g_xh[((size_t)i * BB + b) * KP2 + c] = __float2half(s);
    }
    for (int p = t; p < (KP2 - MIDD) * NN; p += 512) {
        int c = MIDD + p / 36, i = p % 36;
        g_xh[((size_t)i * BB + b) * KP2 + c] = __float2half(0.f);
    }
}

// ------------------------- launch -------------------------
extern "C" void kernel_launch(void* const* d_in, const int* in_sizes, int n_in,
                              void* d_out, int out_size) {
    const float* boxes     = (const float*)d_in[0];
    const float* attention = (const float*)d_in[1];
    const float* features  = (const float*)d_in[2];
    const float* conv_w    = (const float*)d_in[3];
    const float* conv_b    = (const float*)d_in[4];
    const float* skew_wx   = (const float*)d_in[5];
    const float* skew_wy   = (const float*)d_in[6];
    const float* skew_b1   = (const float*)d_in[7];
    const float* skew_w2   = (const float*)d_in[8];
    const float* skew_b2   = (const float*)d_in[9];
    const float* w_ih      = (const float*)d_in[10];
    const float* w_hh      = (const float*)d_in[11];
    const float* b_ih      = (const float*)d_in[12];
    const float* b_hh      = (const float*)d_in[13];
    const float* lr        = (const float*)d_in[14];

    static int attr_done = 0;
    if (!attr_done) {
        cudaFuncSetAttribute(k_conv, cudaFuncAttributeMaxDynamicSharedMemorySize, DYN_CONV);
        cudaFuncSetAttribute(k_gin,  cudaFuncAttributeMaxDynamicSharedMemorySize, DYN_GIN);
        cudaFuncSetAttribute(k_skew, cudaFuncAttributeMaxDynamicSharedMemorySize, DYN_SKEW);
        cudaFuncSetAttribute(k_step, cudaFuncAttributeMaxDynamicSharedMemorySize, DYN_STEP);
        cudaFuncSetAttribute(k_sa,   cudaFuncAttributeMaxDynamicSharedMemorySize, SA_DYN);
        attr_done = 1;
    }

    k_init<<<(BB * OUTD + 255) / 256, 256>>>(boxes);
    {
        size_t total = PN1 + PN2 + PN3 + PN4 + PN5 + PN6 + PN7;
        k_prep<<<(unsigned)((total + 511) / 512), 512>>>(
            conv_w, w_ih, w_hh, features, boxes, attention, skew_wx, skew_wy);
    }
    k_conv<<<dim3(4, 72), 256, DYN_CONV>>>(conv_b);
    k_skew<<<dim3(2, 72), 256, DYN_SKEW>>>();
    k_sa<<<BB, 512, SA_DYN>>>(skew_b1, skew_w2, skew_b2, lr);
    k_gin<<<dim3(18, 32), 512, DYN_GIN>>>(b_ih, b_hh);

    for (int s = 0; s < TSTEPS; s++) {
        k_step<<<128, 256, DYN_STEP>>>(s, s == TSTEPS - 1 ? (float*)d_out : nullptr);
    }
}